// round 11
// baseline (speedup 1.0000x reference)
#include <cuda_runtime.h>
#include <cuda_bf16.h>
#include <cstdint>

#define D      128
#define KN     16
#define MPAD   50048   // 391 * 128

// Scratch (device globals; allocation is forbidden)
__device__ float g_Q[(size_t)MPAD * D];
__device__ float g_K[(size_t)MPAD * D];   // used as bf16 buffer (aliased)
__device__ float g_V[(size_t)MPAD * D];
__device__ float g_A[(size_t)MPAD * D];

// ---------------------------------------------------------------------------
// helpers
// ---------------------------------------------------------------------------
__device__ __forceinline__ uint32_t smem_u32(const void* p) {
    uint32_t a;
    asm("{ .reg .u64 t; cvta.to.shared.u64 t, %1; cvt.u32.u64 %0, t; }"
        : "=r"(a) : "l"(p));
    return a;
}

__device__ __forceinline__ uint32_t f2tf32(float f) {
    uint32_t u;
    asm("cvt.rna.tf32.f32 %0, %1;" : "=r"(u) : "f"(f));
    return u;
}

__device__ __forceinline__ void mma_tf32(float* c, const uint32_t* a, const uint32_t* b) {
    asm volatile(
        "mma.sync.aligned.m16n8k8.row.col.f32.tf32.tf32.f32 "
        "{%0,%1,%2,%3}, {%4,%5,%6,%7}, {%8,%9}, {%0,%1,%2,%3};"
        : "+f"(c[0]), "+f"(c[1]), "+f"(c[2]), "+f"(c[3])
        : "r"(a[0]), "r"(a[1]), "r"(a[2]), "r"(a[3]), "r"(b[0]), "r"(b[1]));
}

#define LDSM_X4(r0, r1, r2, r3, addr) \
    asm volatile("ldmatrix.sync.aligned.m8n8.x4.shared.b16 {%0,%1,%2,%3}, [%4];" \
                 : "=r"(r0), "=r"(r1), "=r"(r2), "=r"(r3) : "r"(addr))

#define SM_STRIDE 132                       // uint32 row stride; 528B rows (16B aligned)
#define SMEM_SZ   (2 * 128 * SM_STRIDE * 4) // A tile + B tile

// ---------------------------------------------------------------------------
// Tensor-core tf32 GEMM + bias: C[M,128] = A[M,128] @ W[128,128] + b
// 128x128 CTA tile, 256 threads / 8 warps (warp tile 32x64), ldmatrix frags.
// blockIdx.y selects (W, bias, C) set; y==1 (K projection) writes bf16 to Kb.
// ---------------------------------------------------------------------------
__global__ __launch_bounds__(256, 1)
void gemm_mma(const float* __restrict__ A,
              const float* __restrict__ W0, const float* __restrict__ W1,
              const float* __restrict__ W2,
              const float* __restrict__ b0, const float* __restrict__ b1,
              const float* __restrict__ b2,
              float* __restrict__ C0, __nv_bfloat16* __restrict__ Kb,
              float* __restrict__ C2,
              int M)
{
    extern __shared__ uint32_t sm[];
    uint32_t* As = sm;                       // As[m][k], stride 132
    uint32_t* Bs = sm + 128 * SM_STRIDE;     // Bs[n][k], stride 132  (B = W^T)

    const int tid = threadIdx.x;
    const int wid = tid >> 5;
    const int lid = tid & 31;
    const int g   = lid >> 2;                // group id 0..7
    const int t   = lid & 3;                 // thread-in-group 0..3
    const int rowBase = blockIdx.x * 128;

    const float* W    = (blockIdx.y == 0) ? W0 : (blockIdx.y == 1) ? W1 : W2;
    const float* bias = (blockIdx.y == 0) ? b0 : (blockIdx.y == 1) ? b1 : b2;

    // ---- Fill A tile [128 x 128] (tf32-converted) ----
#pragma unroll
    for (int i = 0; i < 16; i++) {
        int idx = tid + i * 256;             // float4 index
        int m   = idx >> 5;
        int k4  = (idx & 31) << 2;
        float4 v = make_float4(0.f, 0.f, 0.f, 0.f);
        int gm = rowBase + m;
        if (gm < M) v = *(const float4*)(A + (size_t)gm * D + k4);
        uint32_t* p = As + m * SM_STRIDE + k4;
        p[0] = f2tf32(v.x); p[1] = f2tf32(v.y);
        p[2] = f2tf32(v.z); p[3] = f2tf32(v.w);
    }
    // ---- Fill B tile: Bs[n][k] = tf32(W[k][n]) ----
#pragma unroll
    for (int i = 0; i < 64; i++) {
        int idx = tid + i * 256;
        int k = idx >> 7;
        int n = idx & 127;
        Bs[n * SM_STRIDE + k] = f2tf32(W[(size_t)k * D + n]);
    }
    __syncthreads();

    // ---- Warp tile 32x64: warp_m = (wid&3)*32, warp_n = (wid>>2)*64 ----
    const int warp_m = (wid & 3) * 32;
    const int warp_n = (wid >> 2) * 64;

    // ldmatrix per-lane base addresses (ks = 0)
    // A tiles: lanes 0-15 -> rows (lane&15), lanes 16-31 -> k+4 half
    uint32_t a_addr[2];
#pragma unroll
    for (int mt = 0; mt < 2; mt++) {
        int arow = warp_m + mt * 16 + (lid & 15);
        int acol = (lid >> 4) * 4;
        a_addr[mt] = smem_u32(As + arow * SM_STRIDE + acol);
    }
    // B tiles: x4 covers two n8 blocks; lanes 0-7: n-block0/k0, 8-15: n-block0/k+4,
    //          16-23: n-block1/k0, 24-31: n-block1/k+4
    uint32_t b_addr[4];
#pragma unroll
    for (int np = 0; np < 4; np++) {
        int brow = warp_n + np * 16 + (lid & 7) + ((lid >> 4) << 3);
        int bcol = ((lid >> 3) & 1) * 4;
        b_addr[np] = smem_u32(Bs + brow * SM_STRIDE + bcol);
    }

    float acc[2][8][4];
#pragma unroll
    for (int mt = 0; mt < 2; mt++)
#pragma unroll
        for (int nt = 0; nt < 8; nt++)
#pragma unroll
            for (int j = 0; j < 4; j++) acc[mt][nt][j] = 0.f;

#pragma unroll
    for (int ks = 0; ks < 16; ks++) {
        const uint32_t koff = ks * 32;       // 8 floats = 32 bytes
        uint32_t af[2][4];
        LDSM_X4(af[0][0], af[0][1], af[0][2], af[0][3], a_addr[0] + koff);
        LDSM_X4(af[1][0], af[1][1], af[1][2], af[1][3], a_addr[1] + koff);
        uint32_t bf[8][2];
#pragma unroll
        for (int np = 0; np < 4; np++) {
            LDSM_X4(bf[2 * np][0], bf[2 * np][1], bf[2 * np + 1][0], bf[2 * np + 1][1],
                    b_addr[np] + koff);
        }
#pragma unroll
        for (int mt = 0; mt < 2; mt++)
#pragma unroll
            for (int nt = 0; nt < 8; nt++)
                mma_tf32(acc[mt][nt], af[mt], bf[nt]);
    }

    // ---- Epilogue ----
    if (blockIdx.y == 1) {
        // K projection: write bf16 (attn reads K as bf16; halves gather bytes)
#pragma unroll
        for (int nt = 0; nt < 8; nt++) {
            int col = warp_n + nt * 8 + 2 * t;
            float bx = __ldg(bias + col);
            float by = __ldg(bias + col + 1);
            int gm = rowBase + warp_m + g;
            if (gm < M) {
                *(__nv_bfloat162*)(Kb + (size_t)gm * D + col) =
                    __floats2bfloat162_rn(acc[0][nt][0] + bx, acc[0][nt][1] + by);
            }
            if (gm + 8 < M) {
                *(__nv_bfloat162*)(Kb + (size_t)(gm + 8) * D + col) =
                    __floats2bfloat162_rn(acc[0][nt][2] + bx, acc[0][nt][3] + by);
            }
            int gm2 = gm + 16;
            if (gm2 < M) {
                *(__nv_bfloat162*)(Kb + (size_t)gm2 * D + col) =
                    __floats2bfloat162_rn(acc[1][nt][0] + bx, acc[1][nt][1] + by);
            }
            if (gm2 + 8 < M) {
                *(__nv_bfloat162*)(Kb + (size_t)(gm2 + 8) * D + col) =
                    __floats2bfloat162_rn(acc[1][nt][2] + bx, acc[1][nt][3] + by);
            }
        }
    } else {
        float* C = (blockIdx.y == 0) ? C0 : C2;
#pragma unroll
        for (int nt = 0; nt < 8; nt++) {
            int col = warp_n + nt * 8 + 2 * t;
            float bx = __ldg(bias + col);
            float by = __ldg(bias + col + 1);
#pragma unroll
            for (int mt = 0; mt < 2; mt++) {
                int gm = rowBase + warp_m + mt * 16 + g;
                if (gm < M) {
                    float2 o = make_float2(acc[mt][nt][0] + bx, acc[mt][nt][1] + by);
                    *(float2*)(C + (size_t)gm * D + col) = o;
                }
                if (gm + 8 < M) {
                    float2 o = make_float2(acc[mt][nt][2] + bx, acc[mt][nt][3] + by);
                    *(float2*)(C + (size_t)(gm + 8) * D + col) = o;
                }
            }
        }
    }
}

// ---------------------------------------------------------------------------
// Neighborhood attention v3: one warp per node, row-distributed lanes.
// K rows are bf16 (256B/row -> 8B/lane coalesced); V rows fp32.
// ---------------------------------------------------------------------------
__global__ __launch_bounds__(256)
void attn_kernel(const float* __restrict__ Q,
                 const __nv_bfloat16* __restrict__ Kb,
                 const float* __restrict__ Vm,
                 const int* __restrict__ nbr,
                 float* __restrict__ Out, int N)
{
    const int warp = (blockIdx.x * blockDim.x + threadIdx.x) >> 5;
    if (warp >= N) return;
    const int lane = threadIdx.x & 31;
    const int node = warp;

    // Q row, element-distributed: lane l holds q[l*4 .. l*4+3]
    float4 q4 = *(const float4*)(Q + (size_t)node * D + lane * 4);
    q4.x *= 0.25f; q4.y *= 0.25f; q4.z *= 0.25f; q4.w *= 0.25f; // fold 1/sqrt(16)

    // neighbor ids: lane (l&15) holds id[l&15]
    int my_id = nbr[(size_t)node * KN + (lane & 15)];

    float s[KN];
#pragma unroll
    for (int j = 0; j < KN; j++) {
        int id = __shfl_sync(0xffffffffu, my_id, j);
        int cid = id < 0 ? 0 : (id >= N ? N - 1 : id);
        uint2 raw = *(const uint2*)(Kb + (size_t)cid * D + lane * 4);
        float2 f0 = __bfloat1622float2(*reinterpret_cast<const __nv_bfloat162*>(&raw.x));
        float2 f1 = __bfloat1622float2(*reinterpret_cast<const __nv_bfloat162*>(&raw.y));
        float p = q4.x * f0.x + q4.y * f0.y + q4.z * f1.x + q4.w * f1.y;
        // reduce within the 4 lanes of this head
        p += __shfl_xor_sync(0xffffffffu, p, 1);
        p += __shfl_xor_sync(0xffffffffu, p, 2);
        s[j] = (id < 0) ? -1e9f : p;
    }

    // softmax over 16 neighbors (lane-local: lane holds all scores of its head)
    float m = s[0];
#pragma unroll
    for (int j = 1; j < KN; j++) m = fmaxf(m, s[j]);
    float sum = 0.f;
#pragma unroll
    for (int j = 0; j < KN; j++) { s[j] = __expf(s[j] - m); sum += s[j]; }
    const float inv = 1.0f / sum;

    float4 acc = make_float4(0.f, 0.f, 0.f, 0.f);
#pragma unroll
    for (int j = 0; j < KN; j++) {
        int id = __shfl_sync(0xffffffffu, my_id, j);
        int cid = id < 0 ? 0 : (id >= N ? N - 1 : id);
        float w = s[j] * inv;               // 0 for masked (exp underflow)
        float4 v4 = *(const float4*)(Vm + (size_t)cid * D + lane * 4);
        acc.x = fmaf(w, v4.x, acc.x);
        acc.y = fmaf(w, v4.y, acc.y);
        acc.z = fmaf(w, v4.z, acc.z);
        acc.w = fmaf(w, v4.w, acc.w);
    }

    *(float4*)(Out + (size_t)node * D + lane * 4) = acc;
}

// ---------------------------------------------------------------------------
extern "C" void kernel_launch(void* const* d_in, const int* in_sizes, int n_in,
                              void* d_out, int out_size)
{
    const float* x   = (const float*)d_in[0];
    const int*   nbr = (const int*)d_in[1];
    const float* Wq = (const float*)d_in[2];
    const float* bq = (const float*)d_in[3];
    const float* Wk = (const float*)d_in[4];
    const float* bk = (const float*)d_in[5];
    const float* Wv = (const float*)d_in[6];
    const float* bv = (const float*)d_in[7];
    const float* Wo = (const float*)d_in[8];
    const float* bo = (const float*)d_in[9];
    float* out = (float*)d_out;

    const int N = in_sizes[0] / D;     // 50000

    float *Qp, *Kp, *Vp, *Ap;
    cudaGetSymbolAddress((void**)&Qp, g_Q);
    cudaGetSymbolAddress((void**)&Kp, g_K);
    cudaGetSymbolAddress((void**)&Vp, g_V);
    cudaGetSymbolAddress((void**)&Ap, g_A);
    __nv_bfloat16* Kb = (__nv_bfloat16*)Kp;   // reuse g_K storage as bf16

    cudaFuncSetAttribute(gemm_mma, cudaFuncAttributeMaxDynamicSharedMemorySize, SMEM_SZ);

    const int tiles = (N + 127) / 128;

    // QKV projections in one launch (y: 0=Q fp32, 1=K bf16, 2=V fp32)
    gemm_mma<<<dim3(tiles, 3), 256, SMEM_SZ>>>(x, Wq, Wk, Wv, bq, bk, bv,
                                               Qp, Kb, Vp, N);

    const int attnBlocks = (N + 7) / 8;
    attn_kernel<<<attnBlocks, 256>>>(Qp, Kb, Vp, nbr, Ap, N);

    // Output projection (y==0 -> fp32 path -> out)
    gemm_mma<<<dim3(tiles, 1), 256, SMEM_SZ>>>(Ap, Wo, Wo, Wo, bo, bo, bo,
                                               out, Kb, out, N);
}

// round 12
// speedup vs baseline: 1.0629x; 1.0629x over previous
#include <cuda_runtime.h>
#include <cuda_bf16.h>
#include <cstdint>

#define D      128
#define KN     16
#define MPAD   50048   // 391 * 128

// Scratch (device globals; allocation is forbidden)
__device__ float g_Q[(size_t)MPAD * D];
__device__ float g_K[(size_t)MPAD * D];   // used as bf16 buffer (aliased)
__device__ float g_V[(size_t)MPAD * D];
__device__ float g_A[(size_t)MPAD * D];

// ---------------------------------------------------------------------------
// helpers
// ---------------------------------------------------------------------------
__device__ __forceinline__ uint32_t smem_u32(const void* p) {
    uint32_t a;
    asm("{ .reg .u64 t; cvta.to.shared.u64 t, %1; cvt.u32.u64 %0, t; }"
        : "=r"(a) : "l"(p));
    return a;
}

__device__ __forceinline__ uint32_t f2tf32(float f) {
    uint32_t u;
    asm("cvt.rna.tf32.f32 %0, %1;" : "=r"(u) : "f"(f));
    return u;
}

__device__ __forceinline__ void mma_tf32(float* c, const uint32_t* a, const uint32_t* b) {
    asm volatile(
        "mma.sync.aligned.m16n8k8.row.col.f32.tf32.tf32.f32 "
        "{%0,%1,%2,%3}, {%4,%5,%6,%7}, {%8,%9}, {%0,%1,%2,%3};"
        : "+f"(c[0]), "+f"(c[1]), "+f"(c[2]), "+f"(c[3])
        : "r"(a[0]), "r"(a[1]), "r"(a[2]), "r"(a[3]), "r"(b[0]), "r"(b[1]));
}

#define LDSM_X4(r0, r1, r2, r3, addr) \
    asm volatile("ldmatrix.sync.aligned.m8n8.x4.shared.b16 {%0,%1,%2,%3}, [%4];" \
                 : "=r"(r0), "=r"(r1), "=r"(r2), "=r"(r3) : "r"(addr))

#define SM_STRIDE 132                       // uint32 row stride; 528B rows (16B aligned)
#define SMEM_SZ   (2 * 128 * SM_STRIDE * 4) // A tile + B tile

// ---------------------------------------------------------------------------
// Fused multi-weight tf32 GEMM + bias.
// One CTA owns a 128-row A tile; fills it ONCE, then loops nW weights:
// fill B (vectorized transpose), mainloop (ldmatrix+mma), epilogue.
// nW==3: w=0 -> Q (fp32, C0), w=1 -> K (bf16, Kb), w=2 -> V (fp32, C2).
// nW==1: w=0 -> C0 (fp32).
// ---------------------------------------------------------------------------
__global__ __launch_bounds__(256, 1)
void gemm_fused(const float* __restrict__ A,
                const float* __restrict__ W0, const float* __restrict__ W1,
                const float* __restrict__ W2,
                const float* __restrict__ b0, const float* __restrict__ b1,
                const float* __restrict__ b2,
                float* __restrict__ C0, __nv_bfloat16* __restrict__ Kb,
                float* __restrict__ C2,
                int M, int nW)
{
    extern __shared__ uint32_t sm[];
    uint32_t* As = sm;                       // As[m][k], stride 132
    uint32_t* Bs = sm + 128 * SM_STRIDE;     // Bs[n][k], stride 132  (B = W^T)

    const int tid = threadIdx.x;
    const int wid = tid >> 5;
    const int lid = tid & 31;
    const int g   = lid >> 2;                // group id 0..7
    const int t   = lid & 3;                 // thread-in-group 0..3
    const int rowBase = blockIdx.x * 128;

    // ---- Fill A tile [128 x 128] ONCE (tf32-converted) ----
#pragma unroll
    for (int i = 0; i < 16; i++) {
        int idx = tid + i * 256;             // float4 index
        int m   = idx >> 5;
        int k4  = (idx & 31) << 2;
        float4 v = make_float4(0.f, 0.f, 0.f, 0.f);
        int gm = rowBase + m;
        if (gm < M) v = *(const float4*)(A + (size_t)gm * D + k4);
        uint32_t* p = As + m * SM_STRIDE + k4;
        p[0] = f2tf32(v.x); p[1] = f2tf32(v.y);
        p[2] = f2tf32(v.z); p[3] = f2tf32(v.w);
    }

    // ---- Warp tile 32x64: warp_m = (wid&3)*32, warp_n = (wid>>2)*64 ----
    const int warp_m = (wid & 3) * 32;
    const int warp_n = (wid >> 2) * 64;

    // ldmatrix per-lane base addresses
    uint32_t a_addr[2];
#pragma unroll
    for (int mt = 0; mt < 2; mt++) {
        int arow = warp_m + mt * 16 + (lid & 15);
        int acol = (lid >> 4) * 4;
        a_addr[mt] = smem_u32(As + arow * SM_STRIDE + acol);
    }
    uint32_t b_addr[4];
#pragma unroll
    for (int np = 0; np < 4; np++) {
        int brow = warp_n + np * 16 + (lid & 7) + ((lid >> 4) << 3);
        int bcol = ((lid >> 3) & 1) * 4;
        b_addr[np] = smem_u32(Bs + brow * SM_STRIDE + bcol);
    }

    // B-fill mapping: thread owns n-row (tid&127), k-half (tid>>7)*64.
    const int bf_n  = tid & 127;
    const int bf_kh = (tid >> 7) * 64;

    for (int w = 0; w < nW; w++) {
        const float* W    = (w == 0) ? W0 : (w == 1) ? W1 : W2;
        const float* bias = (w == 0) ? b0 : (w == 1) ? b1 : b2;

        // ---- Fill B tile: Bs[n][k] = tf32(W[k][n]) — vectorized STS.128 ----
#pragma unroll
        for (int j = 0; j < 16; j++) {
            int k0 = bf_kh + j * 4;
            uint32_t q0 = f2tf32(W[(size_t)(k0 + 0) * D + bf_n]);
            uint32_t q1 = f2tf32(W[(size_t)(k0 + 1) * D + bf_n]);
            uint32_t q2 = f2tf32(W[(size_t)(k0 + 2) * D + bf_n]);
            uint32_t q3 = f2tf32(W[(size_t)(k0 + 3) * D + bf_n]);
            uint4 v = make_uint4(q0, q1, q2, q3);
            *(uint4*)(Bs + bf_n * SM_STRIDE + k0) = v;
        }
        __syncthreads();

        // ---- Mainloop ----
        float acc[2][8][4];
#pragma unroll
        for (int mt = 0; mt < 2; mt++)
#pragma unroll
            for (int nt = 0; nt < 8; nt++)
#pragma unroll
                for (int j = 0; j < 4; j++) acc[mt][nt][j] = 0.f;

#pragma unroll
        for (int ks = 0; ks < 16; ks++) {
            const uint32_t koff = ks * 32;   // 8 floats = 32 bytes
            uint32_t af[2][4];
            LDSM_X4(af[0][0], af[0][1], af[0][2], af[0][3], a_addr[0] + koff);
            LDSM_X4(af[1][0], af[1][1], af[1][2], af[1][3], a_addr[1] + koff);
            uint32_t bf[8][2];
#pragma unroll
            for (int np = 0; np < 4; np++) {
                LDSM_X4(bf[2 * np][0], bf[2 * np][1],
                        bf[2 * np + 1][0], bf[2 * np + 1][1], b_addr[np] + koff);
            }
#pragma unroll
            for (int mt = 0; mt < 2; mt++)
#pragma unroll
                for (int nt = 0; nt < 8; nt++)
                    mma_tf32(acc[mt][nt], af[mt], bf[nt]);
        }
        __syncthreads();   // all warps done reading Bs before next fill

        // ---- Epilogue ----
        if (nW == 3 && w == 1) {
            // K projection -> bf16
#pragma unroll
            for (int nt = 0; nt < 8; nt++) {
                int col = warp_n + nt * 8 + 2 * t;
                float bx = __ldg(bias + col);
                float by = __ldg(bias + col + 1);
#pragma unroll
                for (int mt = 0; mt < 2; mt++) {
                    int gm = rowBase + warp_m + mt * 16 + g;
                    if (gm < M) {
                        *(__nv_bfloat162*)(Kb + (size_t)gm * D + col) =
                            __floats2bfloat162_rn(acc[mt][nt][0] + bx, acc[mt][nt][1] + by);
                    }
                    if (gm + 8 < M) {
                        *(__nv_bfloat162*)(Kb + (size_t)(gm + 8) * D + col) =
                            __floats2bfloat162_rn(acc[mt][nt][2] + bx, acc[mt][nt][3] + by);
                    }
                }
            }
        } else {
            float* C = (w == 2) ? C2 : C0;
#pragma unroll
            for (int nt = 0; nt < 8; nt++) {
                int col = warp_n + nt * 8 + 2 * t;
                float bx = __ldg(bias + col);
                float by = __ldg(bias + col + 1);
#pragma unroll
                for (int mt = 0; mt < 2; mt++) {
                    int gm = rowBase + warp_m + mt * 16 + g;
                    if (gm < M) {
                        float2 o = make_float2(acc[mt][nt][0] + bx, acc[mt][nt][1] + by);
                        *(float2*)(C + (size_t)gm * D + col) = o;
                    }
                    if (gm + 8 < M) {
                        float2 o = make_float2(acc[mt][nt][2] + bx, acc[mt][nt][3] + by);
                        *(float2*)(C + (size_t)(gm + 8) * D + col) = o;
                    }
                }
            }
        }
    }
}

// ---------------------------------------------------------------------------
// Neighborhood attention v3: one warp per node, row-distributed lanes.
// K rows are bf16 (256B/row -> 8B/lane coalesced); V rows fp32.
// ---------------------------------------------------------------------------
__global__ __launch_bounds__(256)
void attn_kernel(const float* __restrict__ Q,
                 const __nv_bfloat16* __restrict__ Kb,
                 const float* __restrict__ Vm,
                 const int* __restrict__ nbr,
                 float* __restrict__ Out, int N)
{
    const int warp = (blockIdx.x * blockDim.x + threadIdx.x) >> 5;
    if (warp >= N) return;
    const int lane = threadIdx.x & 31;
    const int node = warp;

    // Q row, element-distributed: lane l holds q[l*4 .. l*4+3]
    float4 q4 = *(const float4*)(Q + (size_t)node * D + lane * 4);
    q4.x *= 0.25f; q4.y *= 0.25f; q4.z *= 0.25f; q4.w *= 0.25f; // fold 1/sqrt(16)

    // neighbor ids: lane (l&15) holds id[l&15]
    int my_id = nbr[(size_t)node * KN + (lane & 15)];

    float s[KN];
#pragma unroll
    for (int j = 0; j < KN; j++) {
        int id = __shfl_sync(0xffffffffu, my_id, j);
        int cid = id < 0 ? 0 : (id >= N ? N - 1 : id);
        uint2 raw = *(const uint2*)(Kb + (size_t)cid * D + lane * 4);
        float2 f0 = __bfloat1622float2(*reinterpret_cast<const __nv_bfloat162*>(&raw.x));
        float2 f1 = __bfloat1622float2(*reinterpret_cast<const __nv_bfloat162*>(&raw.y));
        float p = q4.x * f0.x + q4.y * f0.y + q4.z * f1.x + q4.w * f1.y;
        // reduce within the 4 lanes of this head
        p += __shfl_xor_sync(0xffffffffu, p, 1);
        p += __shfl_xor_sync(0xffffffffu, p, 2);
        s[j] = (id < 0) ? -1e9f : p;
    }

    // softmax over 16 neighbors (lane-local: lane holds all scores of its head)
    float m = s[0];
#pragma unroll
    for (int j = 1; j < KN; j++) m = fmaxf(m, s[j]);
    float sum = 0.f;
#pragma unroll
    for (int j = 0; j < KN; j++) { s[j] = __expf(s[j] - m); sum += s[j]; }
    const float inv = 1.0f / sum;

    float4 acc = make_float4(0.f, 0.f, 0.f, 0.f);
#pragma unroll
    for (int j = 0; j < KN; j++) {
        int id = __shfl_sync(0xffffffffu, my_id, j);
        int cid = id < 0 ? 0 : (id >= N ? N - 1 : id);
        float w = s[j] * inv;               // 0 for masked (exp underflow)
        float4 v4 = *(const float4*)(Vm + (size_t)cid * D + lane * 4);
        acc.x = fmaf(w, v4.x, acc.x);
        acc.y = fmaf(w, v4.y, acc.y);
        acc.z = fmaf(w, v4.z, acc.z);
        acc.w = fmaf(w, v4.w, acc.w);
    }

    *(float4*)(Out + (size_t)node * D + lane * 4) = acc;
}

// ---------------------------------------------------------------------------
extern "C" void kernel_launch(void* const* d_in, const int* in_sizes, int n_in,
                              void* d_out, int out_size)
{
    const float* x   = (const float*)d_in[0];
    const int*   nbr = (const int*)d_in[1];
    const float* Wq = (const float*)d_in[2];
    const float* bq = (const float*)d_in[3];
    const float* Wk = (const float*)d_in[4];
    const float* bk = (const float*)d_in[5];
    const float* Wv = (const float*)d_in[6];
    const float* bv = (const float*)d_in[7];
    const float* Wo = (const float*)d_in[8];
    const float* bo = (const float*)d_in[9];
    float* out = (float*)d_out;

    const int N = in_sizes[0] / D;     // 50000

    float *Qp, *Kp, *Vp, *Ap;
    cudaGetSymbolAddress((void**)&Qp, g_Q);
    cudaGetSymbolAddress((void**)&Kp, g_K);
    cudaGetSymbolAddress((void**)&Vp, g_V);
    cudaGetSymbolAddress((void**)&Ap, g_A);
    __nv_bfloat16* Kb = (__nv_bfloat16*)Kp;   // reuse g_K storage as bf16

    cudaFuncSetAttribute(gemm_fused, cudaFuncAttributeMaxDynamicSharedMemorySize, SMEM_SZ);

    const int tiles = (N + 127) / 128;   // 391

    // Fused QKV: one CTA per A tile, loops 3 weights
    gemm_fused<<<tiles, 256, SMEM_SZ>>>(x, Wq, Wk, Wv, bq, bk, bv,
                                        Qp, Kb, Vp, N, 3);

    const int attnBlocks = (N + 7) / 8;
    attn_kernel<<<attnBlocks, 256>>>(Qp, Kb, Vp, nbr, Ap, N);

    // Output projection (single weight)
    gemm_fused<<<tiles, 256, SMEM_SZ>>>(Ap, Wo, Wo, Wo, bo, bo, bo,
                                        out, Kb, out, N, 1);
}